// round 1
// baseline (speedup 1.0000x reference)
#include <cuda_runtime.h>
#include <math.h>

// Problem constants (B derived at launch; 8192 in this dataset)
#define I_DIM 1024
#define H_DIM 1024
#define RANK  16

// Scratch for low-rank projections: [B, 4*16] each (2 MB each at B=8192)
__device__ float g_xA[8192 * 64];
__device__ float g_hA[8192 * 64];

// ---------------------------------------------------------------------------
// Kernel 1: xA[b, g*16+r] = sum_i x[b,i] * A_i[g,r,i]   (and same for h0/A_h)
// Small GEMM: [B,1024] @ [1024,64]^T.  BM=128, BN=64, BK=16.
// ---------------------------------------------------------------------------
__global__ __launch_bounds__(256) void lora_proj_kernel(
    const float* __restrict__ x, const float* __restrict__ h0,
    const float* __restrict__ A_i, const float* __restrict__ A_h)
{
    const int prob = blockIdx.y;
    const float* __restrict__ src = (prob == 0) ? x : h0;
    const float* __restrict__ Am  = (prob == 0) ? A_i : A_h;
    float* __restrict__ dst       = (prob == 0) ? g_xA : g_hA;

    __shared__ float As[16][128];
    __shared__ float Bs[16][64];

    const int t  = threadIdx.x;
    const int tx = t & 15;   // col group: cols tx*4 .. tx*4+3
    const int ty = t >> 4;   // row group: rows ty*8 .. ty*8+7
    const int bBase = blockIdx.x * 128;

    float acc[8][4];
#pragma unroll
    for (int i = 0; i < 8; i++)
#pragma unroll
        for (int j = 0; j < 4; j++) acc[i][j] = 0.f;

    for (int k0 = 0; k0 < 1024; k0 += 16) {
        // Load A-tile (x rows), transpose into As[kk][row]
#pragma unroll
        for (int j = 0; j < 2; j++) {
            int f   = t * 2 + j;
            int row = f >> 2;
            int kq  = f & 3;
            float4 v = *reinterpret_cast<const float4*>(
                &src[(size_t)(bBase + row) * 1024 + k0 + kq * 4]);
            As[kq * 4 + 0][row] = v.x;
            As[kq * 4 + 1][row] = v.y;
            As[kq * 4 + 2][row] = v.z;
            As[kq * 4 + 3][row] = v.w;
        }
        // Load B-tile (A matrix rows), transpose into Bs[kk][n]
        {
            int n  = t >> 2;   // 0..63
            int kq = t & 3;
            float4 v = *reinterpret_cast<const float4*>(
                &Am[(size_t)n * 1024 + k0 + kq * 4]);
            Bs[kq * 4 + 0][n] = v.x;
            Bs[kq * 4 + 1][n] = v.y;
            Bs[kq * 4 + 2][n] = v.z;
            Bs[kq * 4 + 3][n] = v.w;
        }
        __syncthreads();

#pragma unroll
        for (int kk = 0; kk < 16; kk++) {
            float a[8], b[4];
            *reinterpret_cast<float4*>(&a[0]) =
                *reinterpret_cast<const float4*>(&As[kk][ty * 8]);
            *reinterpret_cast<float4*>(&a[4]) =
                *reinterpret_cast<const float4*>(&As[kk][ty * 8 + 4]);
            *reinterpret_cast<float4*>(&b[0]) =
                *reinterpret_cast<const float4*>(&Bs[kk][tx * 4]);
#pragma unroll
            for (int i = 0; i < 8; i++)
#pragma unroll
                for (int j = 0; j < 4; j++)
                    acc[i][j] += a[i] * b[j];
        }
        __syncthreads();
    }

#pragma unroll
    for (int i = 0; i < 8; i++) {
        int row = bBase + ty * 8 + i;
        float4 v = make_float4(acc[i][0], acc[i][1], acc[i][2], acc[i][3]);
        *reinterpret_cast<float4*>(&dst[(size_t)row * 64 + tx * 4]) = v;
    }
}

// ---------------------------------------------------------------------------
// Kernel 2: fused main GEMM + LoRA correction + bias + LSTM cell epilogue.
// CTA tile: 128 batch rows x (4 gates * 32 h-cols).  K = I + H = 2048, BK=16.
// Thread (tx,ty): rows ty*8..+7, cols n = g*32 + tx*2 + p  (g=0..3, p=0..1),
// i.e. acc[i][g*2+p] -> all 4 gates of h = hBase + tx*2 + p live in one thread.
// ---------------------------------------------------------------------------
__global__ __launch_bounds__(256) void lstm_main_kernel(
    const float* __restrict__ x,  const float* __restrict__ h0,
    const float* __restrict__ c0,
    const float* __restrict__ W_i, const float* __restrict__ W_h,
    const float* __restrict__ b_i, const float* __restrict__ b_h,
    const float* __restrict__ Bi,  const float* __restrict__ Bh,
    float* __restrict__ out, int B)
{
    __shared__ __align__(16) float smem[10240];   // 40 KB, aliased
    float (*As)[128] = reinterpret_cast<float(*)[128]>(smem);          // [16][128]
    float (*Bs)[128] = reinterpret_cast<float(*)[128]>(smem + 2048);   // [16][128]

    const int t  = threadIdx.x;
    const int tx = t & 15;
    const int ty = t >> 4;
    const int bBase = blockIdx.x * 128;
    const int hBase = blockIdx.y * 32;

    float acc[8][8];
#pragma unroll
    for (int i = 0; i < 8; i++)
#pragma unroll
        for (int j = 0; j < 8; j++) acc[i][j] = 0.f;

    // -------- main GEMM over K = 2048 (phase 0: x/W_i, phase 1: h0/W_h) ----
    for (int kt = 0; kt < 128; kt++) {
        const int k0 = kt * 16;
        const float* Ap;
        const float* Wp;
        int kOff;
        if (k0 < 1024) { Ap = x;  Wp = W_i; kOff = k0; }
        else           { Ap = h0; Wp = W_h; kOff = k0 - 1024; }

        // A tile: x/h0 rows, transposed
#pragma unroll
        for (int j = 0; j < 2; j++) {
            int f   = t * 2 + j;
            int row = f >> 2;
            int kq  = f & 3;
            float4 v = *reinterpret_cast<const float4*>(
                &Ap[(size_t)(bBase + row) * 1024 + kOff + kq * 4]);
            As[kq * 4 + 0][row] = v.x;
            As[kq * 4 + 1][row] = v.y;
            As[kq * 4 + 2][row] = v.z;
            As[kq * 4 + 3][row] = v.w;
        }
        // B tile: weights. n = g*32 + hh; W[g, hBase+hh, k] row-major in k.
#pragma unroll
        for (int j = 0; j < 2; j++) {
            int f  = t * 2 + j;
            int n  = f >> 2;
            int kq = f & 3;
            int g  = n >> 5;
            int hh = n & 31;
            float4 v = *reinterpret_cast<const float4*>(
                &Wp[((size_t)g * 1024 + hBase + hh) * 1024 + kOff + kq * 4]);
            Bs[kq * 4 + 0][n] = v.x;
            Bs[kq * 4 + 1][n] = v.y;
            Bs[kq * 4 + 2][n] = v.z;
            Bs[kq * 4 + 3][n] = v.w;
        }
        __syncthreads();

#pragma unroll
        for (int kk = 0; kk < 16; kk++) {
            float a[8], b[8];
            *reinterpret_cast<float4*>(&a[0]) =
                *reinterpret_cast<const float4*>(&As[kk][ty * 8]);
            *reinterpret_cast<float4*>(&a[4]) =
                *reinterpret_cast<const float4*>(&As[kk][ty * 8 + 4]);
#pragma unroll
            for (int g = 0; g < 4; g++) {
                float2 bv = *reinterpret_cast<const float2*>(&Bs[kk][g * 32 + tx * 2]);
                b[g * 2 + 0] = bv.x;
                b[g * 2 + 1] = bv.y;
            }
#pragma unroll
            for (int i = 0; i < 8; i++)
#pragma unroll
                for (int j = 0; j < 8; j++)
                    acc[i][j] += a[i] * b[j];
        }
        __syncthreads();
    }

    // -------- LoRA correction: two passes (x-side, then h-side) ------------
    float (*sLA)[64] = reinterpret_cast<float(*)[64]>(smem);           // [128][64]
    float (*sLB)[16] = reinterpret_cast<float(*)[16]>(smem + 8192);    // [128][16]

    const float* lA = g_xA;
    const float* lB = Bi;
#pragma unroll
    for (int pass = 0; pass < 2; pass++) {
        __syncthreads();
        // low-rank activations for this batch tile: [128][64]
#pragma unroll
        for (int j = 0; j < 8; j++) {
            int f   = t + 256 * j;
            int row = f >> 4;
            int c4  = f & 15;
            *reinterpret_cast<float4*>(&sLA[row][c4 * 4]) =
                *reinterpret_cast<const float4*>(&lA[(size_t)(bBase + row) * 64 + c4 * 4]);
        }
        // B-matrix slice for this h tile: [g*32+hh][r]
#pragma unroll
        for (int j = 0; j < 2; j++) {
            int f   = t * 2 + j;
            int ghh = f >> 2;
            int rq  = f & 3;
            int g   = ghh >> 5;
            int hh  = ghh & 31;
            *reinterpret_cast<float4*>(&sLB[ghh][rq * 4]) =
                *reinterpret_cast<const float4*>(
                    &lB[((size_t)g * 1024 + hBase + hh) * 16 + rq * 4]);
        }
        __syncthreads();

#pragma unroll
        for (int i = 0; i < 8; i++) {
            int row = ty * 8 + i;
#pragma unroll
            for (int g = 0; g < 4; g++) {
#pragma unroll
                for (int p = 0; p < 2; p++) {
                    int hh = tx * 2 + p;
                    float s = 0.f;
#pragma unroll
                    for (int r = 0; r < 16; r++)
                        s += sLA[row][g * 16 + r] * sLB[g * 32 + hh][r];
                    acc[i][g * 2 + p] += s;
                }
            }
        }
        lA = g_hA;
        lB = Bh;
    }

    // -------- bias + activations + cell update + store ---------------------
    const size_t outC = (size_t)B * 1024;   // offset of c_t block
#pragma unroll
    for (int i = 0; i < 8; i++) {
        int b = bBase + ty * 8 + i;
#pragma unroll
        for (int p = 0; p < 2; p++) {
            int h = hBase + tx * 2 + p;
            float pi = acc[i][0 + p] + b_i[0 * 1024 + h] + b_h[0 * 1024 + h];
            float pf = acc[i][2 + p] + b_i[1 * 1024 + h] + b_h[1 * 1024 + h];
            float pg = acc[i][4 + p] + b_i[2 * 1024 + h] + b_h[2 * 1024 + h];
            float po = acc[i][6 + p] + b_i[3 * 1024 + h] + b_h[3 * 1024 + h];

            float it = 1.f / (1.f + expf(-pi));
            float ft = 1.f / (1.f + expf(-pf));
            float gt = tanhf(pg);
            float ot = 1.f / (1.f + expf(-po));

            float cv = ft * c0[(size_t)b * 1024 + h] + it * gt;
            float hv = ot * tanhf(cv);

            out[(size_t)b * 1024 + h]        = hv;
            out[outC + (size_t)b * 1024 + h] = cv;
        }
    }
}

// ---------------------------------------------------------------------------
extern "C" void kernel_launch(void* const* d_in, const int* in_sizes, int n_in,
                              void* d_out, int out_size)
{
    const float* x   = (const float*)d_in[0];
    const float* h0  = (const float*)d_in[1];
    const float* c0  = (const float*)d_in[2];
    const float* W_i = (const float*)d_in[3];
    const float* W_h = (const float*)d_in[4];
    const float* b_i = (const float*)d_in[5];
    const float* b_h = (const float*)d_in[6];
    const float* A_i = (const float*)d_in[7];
    const float* B_i = (const float*)d_in[8];
    const float* A_h = (const float*)d_in[9];
    const float* B_h = (const float*)d_in[10];

    const int B = in_sizes[0] / I_DIM;   // 8192

    dim3 g1(B / 128, 2);
    lora_proj_kernel<<<g1, 256>>>(x, h0, A_i, A_h);

    dim3 g2(B / 128, H_DIM / 32);
    lstm_main_kernel<<<g2, 256>>>(x, h0, c0, W_i, W_h, b_i, b_h, B_i, B_h,
                                  (float*)d_out, B);
}

// round 3
// speedup vs baseline: 2.7689x; 2.7689x over previous
#include <cuda_runtime.h>
#include <cuda_bf16.h>
#include <cstdint>
#include <math.h>

// ---------------------------------------------------------------------------
// Problem constants
// ---------------------------------------------------------------------------
#define B_MAX 8192
#define I_DIM 1024
#define KAUG  2176          // 1024 (x) + 1024 (h0) + 64 (xA) + 64 (hA)
#define NAUG  4096          // 4 gates * 1024 h, reordered n' = h*4 + g
#define NCHUNK 68           // KAUG / 32
#define BM 128
#define BN 128

// ---------------------------------------------------------------------------
// Device scratch (no allocations allowed)
// ---------------------------------------------------------------------------
__device__ float g_xA[B_MAX * 64];
__device__ float g_hA[B_MAX * 64];
__device__ __nv_bfloat16 gA_hi[(size_t)B_MAX * KAUG];
__device__ __nv_bfloat16 gA_lo[(size_t)B_MAX * KAUG];
__device__ __nv_bfloat16 gW_hi[(size_t)NAUG * KAUG];
__device__ __nv_bfloat16 gW_lo[(size_t)NAUG * KAUG];

// ---------------------------------------------------------------------------
// Helpers
// ---------------------------------------------------------------------------
__device__ __forceinline__ uint32_t smem_u32(const void* p) {
    uint32_t a;
    asm("{ .reg .u64 t; cvta.to.shared.u64 t, %1; cvt.u32.u64 %0, t; }"
        : "=r"(a) : "l"(p));
    return a;
}

// Tile = 128 rows x 64B. Swizzle 16B chunks within 128B lines by line index.
__device__ __forceinline__ uint32_t swz(uint32_t o) {
    return o ^ (((o >> 7) & 7) << 4);
}

__device__ __forceinline__ void cp16(uint32_t dst, const void* src) {
    asm volatile("cp.async.cg.shared.global [%0], [%1], 16;"
                 :: "r"(dst), "l"(src));
}
#define CP_COMMIT() asm volatile("cp.async.commit_group;" ::: "memory")

#define LDSM_X4(r0, r1, r2, r3, addr)                                         \
    asm volatile("ldmatrix.sync.aligned.m8n8.x4.shared.b16 "                  \
                 "{%0,%1,%2,%3}, [%4];"                                       \
                 : "=r"(r0), "=r"(r1), "=r"(r2), "=r"(r3) : "r"(addr))

#define MMA_BF16(d, a, b)                                                     \
    asm volatile("mma.sync.aligned.m16n8k16.row.col.f32.bf16.bf16.f32 "       \
                 "{%0,%1,%2,%3}, {%4,%5,%6,%7}, {%8,%9}, {%0,%1,%2,%3};"      \
                 : "+f"((d)[0]), "+f"((d)[1]), "+f"((d)[2]), "+f"((d)[3])     \
                 : "r"((a)[0]), "r"((a)[1]), "r"((a)[2]), "r"((a)[3]),        \
                   "r"((b)[0]), "r"((b)[1]))

// ---------------------------------------------------------------------------
// Kernel 1: LoRA low-rank projections (fp32 SIMT; ~2 GFLOP)
// ---------------------------------------------------------------------------
__global__ __launch_bounds__(256) void lora_proj_kernel(
    const float* __restrict__ x, const float* __restrict__ h0,
    const float* __restrict__ A_i, const float* __restrict__ A_h)
{
    const int prob = blockIdx.y;
    const float* __restrict__ src = (prob == 0) ? x : h0;
    const float* __restrict__ Am  = (prob == 0) ? A_i : A_h;
    float* __restrict__ dst       = (prob == 0) ? g_xA : g_hA;

    __shared__ float As[16][128];
    __shared__ float Bs[16][64];

    const int t  = threadIdx.x;
    const int tx = t & 15;
    const int ty = t >> 4;
    const int bBase = blockIdx.x * 128;

    float acc[8][4];
#pragma unroll
    for (int i = 0; i < 8; i++)
#pragma unroll
        for (int j = 0; j < 4; j++) acc[i][j] = 0.f;

    for (int k0 = 0; k0 < 1024; k0 += 16) {
#pragma unroll
        for (int j = 0; j < 2; j++) {
            int f = t * 2 + j;
            int row = f >> 2, kq = f & 3;
            float4 v = *reinterpret_cast<const float4*>(
                &src[(size_t)(bBase + row) * 1024 + k0 + kq * 4]);
            As[kq * 4 + 0][row] = v.x; As[kq * 4 + 1][row] = v.y;
            As[kq * 4 + 2][row] = v.z; As[kq * 4 + 3][row] = v.w;
        }
        {
            int n = t >> 2, kq = t & 3;
            float4 v = *reinterpret_cast<const float4*>(
                &Am[(size_t)n * 1024 + k0 + kq * 4]);
            Bs[kq * 4 + 0][n] = v.x; Bs[kq * 4 + 1][n] = v.y;
            Bs[kq * 4 + 2][n] = v.z; Bs[kq * 4 + 3][n] = v.w;
        }
        __syncthreads();
#pragma unroll
        for (int kk = 0; kk < 16; kk++) {
            float a[8], b[4];
            *reinterpret_cast<float4*>(&a[0]) =
                *reinterpret_cast<const float4*>(&As[kk][ty * 8]);
            *reinterpret_cast<float4*>(&a[4]) =
                *reinterpret_cast<const float4*>(&As[kk][ty * 8 + 4]);
            *reinterpret_cast<float4*>(&b[0]) =
                *reinterpret_cast<const float4*>(&Bs[kk][tx * 4]);
#pragma unroll
            for (int i = 0; i < 8; i++)
#pragma unroll
                for (int j = 0; j < 4; j++)
                    acc[i][j] += a[i] * b[j];
        }
        __syncthreads();
    }
#pragma unroll
    for (int i = 0; i < 8; i++) {
        int row = bBase + ty * 8 + i;
        float4 v = make_float4(acc[i][0], acc[i][1], acc[i][2], acc[i][3]);
        *reinterpret_cast<float4*>(&dst[(size_t)row * 64 + tx * 4]) = v;
    }
}

// ---------------------------------------------------------------------------
// Kernel 2a: build augmented A operand (bf16 hi/lo).
// Row b: [x(1024) | h0(1024) | xA(64) | hA(64)]
// ---------------------------------------------------------------------------
__global__ __launch_bounds__(256) void convert_A_kernel(
    const float* __restrict__ x, const float* __restrict__ h0, int B)
{
    size_t e = (size_t)blockIdx.x * 256 + threadIdx.x;
    size_t total = (size_t)B * KAUG;
    if (e >= total) return;
    int b = (int)(e / KAUG);
    int k = (int)(e % KAUG);
    float v;
    if (k < 1024)      v = x[(size_t)b * 1024 + k];
    else if (k < 2048) v = h0[(size_t)b * 1024 + (k - 1024)];
    else if (k < 2112) v = g_xA[(size_t)b * 64 + (k - 2048)];
    else               v = g_hA[(size_t)b * 64 + (k - 2112)];
    __nv_bfloat16 hi = __float2bfloat16(v);
    float rem = v - __bfloat162float(hi);
    gA_hi[e] = hi;
    gA_lo[e] = __float2bfloat16(rem);
}

// ---------------------------------------------------------------------------
// Kernel 2b: build augmented W operand (bf16 hi/lo), N reordered n' = h*4 + g.
// ---------------------------------------------------------------------------
__global__ __launch_bounds__(256) void convert_W_kernel(
    const float* __restrict__ W_i, const float* __restrict__ W_h,
    const float* __restrict__ Bi,  const float* __restrict__ Bh)
{
    size_t e = (size_t)blockIdx.x * 256 + threadIdx.x;
    if (e >= (size_t)NAUG * KAUG) return;
    int n = (int)(e / KAUG);
    int k = (int)(e % KAUG);
    int g = n & 3;
    int h = n >> 2;
    float v;
    if (k < 1024) {
        v = W_i[((size_t)g * 1024 + h) * 1024 + k];
    } else if (k < 2048) {
        v = W_h[((size_t)g * 1024 + h) * 1024 + (k - 1024)];
    } else if (k < 2112) {
        int kk = k - 2048;
        v = ((kk >> 4) == g) ? Bi[((size_t)g * 1024 + h) * 16 + (kk & 15)] : 0.f;
    } else {
        int kk = k - 2112;
        v = ((kk >> 4) == g) ? Bh[((size_t)g * 1024 + h) * 16 + (kk & 15)] : 0.f;
    }
    __nv_bfloat16 hi = __float2bfloat16(v);
    float rem = v - __bfloat162float(hi);
    gW_hi[e] = hi;
    gW_lo[e] = __float2bfloat16(rem);
}

// ---------------------------------------------------------------------------
// Main kernel: mma.sync bf16 (3-product fp32 emulation) + fused LSTM epilogue.
// CTA 128x128, K chunks of 32, 3-stage cp.async pipeline.
// Stage layout (32 KB): A_hi 8K | A_lo 8K | B_hi 8K | B_lo 8K.
// ---------------------------------------------------------------------------
static constexpr int STG = 32768;
static constexpr int OFF_A_HI = 0;
static constexpr int OFF_A_LO = 8192;
static constexpr int OFF_B_HI = 16384;
static constexpr int OFF_B_LO = 24576;
static constexpr int OFF_BIAS = 3 * STG;              // 98304
static constexpr int SMEM_DYN = OFF_BIAS + 512 + 1024; // + align slack

__device__ __forceinline__ void load_chunk(uint32_t sb, int stage, int chunk,
                                           int bBase, int nBase, int t)
{
    const uint32_t stg = sb + stage * STG;
    const int kbase = chunk * 32;
#pragma unroll
    for (int it = 0; it < 2; it++) {
        int f = t + 256 * it;              // 0..511
        int row = f >> 2, c16 = f & 3;
        uint32_t sw = swz((uint32_t)(row * 64 + c16 * 16));
        size_t giA = (size_t)(bBase + row) * KAUG + kbase + c16 * 8;
        size_t giB = (size_t)(nBase + row) * KAUG + kbase + c16 * 8;
        cp16(stg + OFF_A_HI + sw, &gA_hi[giA]);
        cp16(stg + OFF_A_LO + sw, &gA_lo[giA]);
        cp16(stg + OFF_B_HI + sw, &gW_hi[giB]);
        cp16(stg + OFF_B_LO + sw, &gW_lo[giB]);
    }
    CP_COMMIT();
}

__global__ __launch_bounds__(256, 1) void lstm_mma_kernel(
    const float* __restrict__ c0,
    const float* __restrict__ b_i, const float* __restrict__ b_h,
    float* __restrict__ out, int B)
{
    extern __shared__ char smem_raw[];
    uint32_t sb_raw = smem_u32(smem_raw);
    uint32_t sb = (sb_raw + 127) & ~127u;
    char* smem = smem_raw + (sb - sb_raw);

    const int t = threadIdx.x;
    const int l = t & 31;
    const int wid = t >> 5;
    const int wm = wid >> 2;        // 0..1  (M: 64 rows each)
    const int wn = wid & 3;         // 0..3  (N: 32 cols each)
    const int bBase = blockIdx.x * BM;
    const int nBase = blockIdx.y * BN;

    // bias for this N tile
    float* biasp = reinterpret_cast<float*>(smem + OFF_BIAS);
    if (t < 128) {
        int n = nBase + t;
        int g = n & 3, h = n >> 2;
        biasp[t] = b_i[g * 1024 + h] + b_h[g * 1024 + h];
    }

    float acc[4][4][4];
#pragma unroll
    for (int mi = 0; mi < 4; mi++)
#pragma unroll
        for (int ni = 0; ni < 4; ni++)
#pragma unroll
            for (int e = 0; e < 4; e++) acc[mi][ni][e] = 0.f;

    // prologue: stages 0,1
    load_chunk(sb, 0, 0, bBase, nBase, t);
    load_chunk(sb, 1, 1, bBase, nBase, t);

    for (int i = 0; i < NCHUNK; i++) {
        if (i < NCHUNK - 1) {
            asm volatile("cp.async.wait_group 1;" ::: "memory");
        } else {
            asm volatile("cp.async.wait_group 0;" ::: "memory");
        }
        __syncthreads();
        if (i + 2 < NCHUNK) load_chunk(sb, (i + 2) % 3, i + 2, bBase, nBase, t);

        const uint32_t stg = sb + (i % 3) * STG;

#pragma unroll
        for (int s = 0; s < 2; s++) {
            uint32_t a_hi[4][4], a_lo[4][4];
#pragma unroll
            for (int mi = 0; mi < 4; mi++) {
                int row = wm * 64 + mi * 16 + (l & 15);
                int c16 = s * 2 + (l >> 4);
                uint32_t o = swz((uint32_t)(row * 64 + c16 * 16));
                LDSM_X4(a_hi[mi][0], a_hi[mi][1], a_hi[mi][2], a_hi[mi][3],
                        stg + OFF_A_HI + o);
                LDSM_X4(a_lo[mi][0], a_lo[mi][1], a_lo[mi][2], a_lo[mi][3],
                        stg + OFF_A_LO + o);
            }
            uint32_t b_hi[4][2], b_lo[4][2];
#pragma unroll
            for (int p = 0; p < 2; p++) {
                int row = wn * 32 + p * 16 + ((l >> 4) & 1) * 8 + (l & 7);
                int c16 = s * 2 + ((l >> 3) & 1);
                uint32_t o = swz((uint32_t)(row * 64 + c16 * 16));
                uint32_t r0, r1, r2, r3;
                LDSM_X4(r0, r1, r2, r3, stg + OFF_B_HI + o);
                b_hi[p * 2][0] = r0;  b_hi[p * 2][1] = r1;
                b_hi[p * 2 + 1][0] = r2; b_hi[p * 2 + 1][1] = r3;
                LDSM_X4(r0, r1, r2, r3, stg + OFF_B_LO + o);
                b_lo[p * 2][0] = r0;  b_lo[p * 2][1] = r1;
                b_lo[p * 2 + 1][0] = r2; b_lo[p * 2 + 1][1] = r3;
            }
#pragma unroll
            for (int mi = 0; mi < 4; mi++) {
#pragma unroll
                for (int ni = 0; ni < 4; ni++) {
                    MMA_BF16(acc[mi][ni], a_hi[mi], b_hi[ni]);
                    MMA_BF16(acc[mi][ni], a_hi[mi], b_lo[ni]);
                    MMA_BF16(acc[mi][ni], a_lo[mi], b_hi[ni]);
                }
            }
        }
    }

    // ------------------- epilogue: stage accs through SMEM -----------------
    __syncthreads();
    float* ebuf = reinterpret_cast<float*>(smem);   // [128][132] fp32
#pragma unroll
    for (int mi = 0; mi < 4; mi++) {
#pragma unroll
        for (int ni = 0; ni < 4; ni++) {
            int r0 = wm * 64 + mi * 16 + (l >> 2);
            int c  = wn * 32 + ni * 8 + (l & 3) * 2;
            ebuf[r0 * 132 + c]           = acc[mi][ni][0];
            ebuf[r0 * 132 + c + 1]       = acc[mi][ni][1];
            ebuf[(r0 + 8) * 132 + c]     = acc[mi][ni][2];
            ebuf[(r0 + 8) * 132 + c + 1] = acc[mi][ni][3];
        }
    }
    __syncthreads();

    const int rb = t >> 1;
    const int hoff = (t & 1) * 16;
    const size_t b = (size_t)(bBase + rb);
    const int hbase = (nBase >> 2) + hoff;
    const size_t outC = (size_t)B * 1024;

    float cin[16];
#pragma unroll
    for (int q = 0; q < 4; q++) {
        float4 v = *reinterpret_cast<const float4*>(&c0[b * 1024 + hbase + q * 4]);
        cin[q * 4 + 0] = v.x; cin[q * 4 + 1] = v.y;
        cin[q * 4 + 2] = v.z; cin[q * 4 + 3] = v.w;
    }

    float hv[16], cv[16];
#pragma unroll
    for (int j = 0; j < 16; j++) {
        int nl = (hoff + j) * 4;
        const float* p = &ebuf[rb * 132 + nl];
        float pi = p[0] + biasp[nl + 0];
        float pf = p[1] + biasp[nl + 1];
        float pg = p[2] + biasp[nl + 2];
        float po = p[3] + biasp[nl + 3];

        float it = 1.f / (1.f + __expf(-pi));
        float ft = 1.f / (1.f + __expf(-pf));
        float gt = 1.f - 2.f / (__expf(2.f * pg) + 1.f);
        float ot = 1.f / (1.f + __expf(-po));

        float c = ft * cin[j] + it * gt;
        cv[j] = c;
        hv[j] = ot * (1.f - 2.f / (__expf(2.f * c) + 1.f));
    }
#pragma unroll
    for (int q = 0; q < 4; q++) {
        *reinterpret_cast<float4*>(&out[b * 1024 + hbase + q * 4]) =
            make_float4(hv[q * 4], hv[q * 4 + 1], hv[q * 4 + 2], hv[q * 4 + 3]);
        *reinterpret_cast<float4*>(&out[outC + b * 1024 + hbase + q * 4]) =
            make_float4(cv[q * 4], cv[q * 4 + 1], cv[q * 4 + 2], cv[q * 4 + 3]);
    }
}

// ---------------------------------------------------------------------------
extern "C" void kernel_launch(void* const* d_in, const int* in_sizes, int n_in,
                              void* d_out, int out_size)
{
    const float* x   = (const float*)d_in[0];
    const float* h0  = (const float*)d_in[1];
    const float* c0  = (const float*)d_in[2];
    const float* W_i = (const float*)d_in[3];
    const float* W_h = (const float*)d_in[4];
    const float* b_i = (const float*)d_in[5];
    const float* b_h = (const float*)d_in[6];
    const float* A_i = (const float*)d_in[7];
    const float* B_i = (const float*)d_in[8];
    const float* A_h = (const float*)d_in[9];
    const float* B_h = (const float*)d_in[10];

    const int B = in_sizes[0] / I_DIM;   // 8192

    // 1) LoRA rank-16 projections
    dim3 g1(B / 128, 2);
    lora_proj_kernel<<<g1, 256>>>(x, h0, A_i, A_h);

    // 2) Build bf16 hi/lo augmented operands
    {
        size_t elemsA = (size_t)B * KAUG;
        convert_A_kernel<<<(unsigned)((elemsA + 255) / 256), 256>>>(x, h0, B);
        size_t elemsW = (size_t)NAUG * KAUG;
        convert_W_kernel<<<(unsigned)((elemsW + 255) / 256), 256>>>(W_i, W_h, B_i, B_h);
    }

    // 3) Main tensor-core GEMM + fused LSTM epilogue
    cudaFuncSetAttribute(lstm_mma_kernel,
                         cudaFuncAttributeMaxDynamicSharedMemorySize, SMEM_DYN);
    dim3 g3(B / BM, NAUG / BN);
    lstm_mma_kernel<<<g3, 256, SMEM_DYN>>>(c0, b_i, b_h, (float*)d_out, B);
}

// round 4
// speedup vs baseline: 3.1906x; 1.1523x over previous
#include <cuda_runtime.h>
#include <cuda_bf16.h>
#include <cstdint>
#include <math.h>

// ---------------------------------------------------------------------------
// Problem constants
// ---------------------------------------------------------------------------
#define B_MAX 8192
#define I_DIM 1024
#define KAUG  2176          // 1024 (x) + 1024 (h0) + 64 (xA) + 64 (hA)
#define NAUG  4096          // 4 gates * 1024 h, reordered n' = h*4 + g
#define KC    64
#define NCHUNK 34           // KAUG / KC
#define BM 128
#define BN 128

// ---------------------------------------------------------------------------
// Device scratch (no allocations allowed)
// ---------------------------------------------------------------------------
__device__ float g_xA[B_MAX * 64];
__device__ float g_hA[B_MAX * 64];
__device__ __nv_bfloat16 gA_hi[(size_t)B_MAX * KAUG];
__device__ __nv_bfloat16 gA_lo[(size_t)B_MAX * KAUG];
__device__ __nv_bfloat16 gW_hi[(size_t)NAUG * KAUG];
__device__ __nv_bfloat16 gW_lo[(size_t)NAUG * KAUG];

// ---------------------------------------------------------------------------
// Helpers
// ---------------------------------------------------------------------------
__device__ __forceinline__ uint32_t smem_u32(const void* p) {
    uint32_t a;
    asm("{ .reg .u64 t; cvta.to.shared.u64 t, %1; cvt.u32.u64 %0, t; }"
        : "=r"(a) : "l"(p));
    return a;
}

// Tiles are 128B-wide rows. Standard SW128: XOR 16B-chunk index with row&7.
__device__ __forceinline__ uint32_t swz(uint32_t o) {
    return o ^ (((o >> 7) & 7) << 4);
}

__device__ __forceinline__ void cp16(uint32_t dst, const void* src) {
    asm volatile("cp.async.cg.shared.global [%0], [%1], 16;"
                 :: "r"(dst), "l"(src));
}
#define CP_COMMIT() asm volatile("cp.async.commit_group;" ::: "memory")

#define LDSM_X4(r0, r1, r2, r3, addr)                                         \
    asm volatile("ldmatrix.sync.aligned.m8n8.x4.shared.b16 "                  \
                 "{%0,%1,%2,%3}, [%4];"                                       \
                 : "=r"(r0), "=r"(r1), "=r"(r2), "=r"(r3) : "r"(addr))

#define MMA_BF16(d, a, b)                                                     \
    asm volatile("mma.sync.aligned.m16n8k16.row.col.f32.bf16.bf16.f32 "       \
                 "{%0,%1,%2,%3}, {%4,%5,%6,%7}, {%8,%9}, {%0,%1,%2,%3};"      \
                 : "+f"((d)[0]), "+f"((d)[1]), "+f"((d)[2]), "+f"((d)[3])     \
                 : "r"((a)[0]), "r"((a)[1]), "r"((a)[2]), "r"((a)[3]),        \
                   "r"((b)[0]), "r"((b)[1]))

// ---------------------------------------------------------------------------
// Kernel 1: LoRA low-rank projections (fp32 SIMT; ~2 GFLOP)
// ---------------------------------------------------------------------------
__global__ __launch_bounds__(256) void lora_proj_kernel(
    const float* __restrict__ x, const float* __restrict__ h0,
    const float* __restrict__ A_i, const float* __restrict__ A_h)
{
    const int prob = blockIdx.y;
    const float* __restrict__ src = (prob == 0) ? x : h0;
    const float* __restrict__ Am  = (prob == 0) ? A_i : A_h;
    float* __restrict__ dst       = (prob == 0) ? g_xA : g_hA;

    __shared__ float As[16][128];
    __shared__ float Bs[16][64];

    const int t  = threadIdx.x;
    const int tx = t & 15;
    const int ty = t >> 4;
    const int bBase = blockIdx.x * 128;

    float acc[8][4];
#pragma unroll
    for (int i = 0; i < 8; i++)
#pragma unroll
        for (int j = 0; j < 4; j++) acc[i][j] = 0.f;

    for (int k0 = 0; k0 < 1024; k0 += 16) {
#pragma unroll
        for (int j = 0; j < 2; j++) {
            int f = t * 2 + j;
            int row = f >> 2, kq = f & 3;
            float4 v = *reinterpret_cast<const float4*>(
                &src[(size_t)(bBase + row) * 1024 + k0 + kq * 4]);
            As[kq * 4 + 0][row] = v.x; As[kq * 4 + 1][row] = v.y;
            As[kq * 4 + 2][row] = v.z; As[kq * 4 + 3][row] = v.w;
        }
        {
            int n = t >> 2, kq = t & 3;
            float4 v = *reinterpret_cast<const float4*>(
                &Am[(size_t)n * 1024 + k0 + kq * 4]);
            Bs[kq * 4 + 0][n] = v.x; Bs[kq * 4 + 1][n] = v.y;
            Bs[kq * 4 + 2][n] = v.z; Bs[kq * 4 + 3][n] = v.w;
        }
        __syncthreads();
#pragma unroll
        for (int kk = 0; kk < 16; kk++) {
            float a[8], b[4];
            *reinterpret_cast<float4*>(&a[0]) =
                *reinterpret_cast<const float4*>(&As[kk][ty * 8]);
            *reinterpret_cast<float4*>(&a[4]) =
                *reinterpret_cast<const float4*>(&As[kk][ty * 8 + 4]);
            *reinterpret_cast<float4*>(&b[0]) =
                *reinterpret_cast<const float4*>(&Bs[kk][tx * 4]);
#pragma unroll
            for (int i = 0; i < 8; i++)
#pragma unroll
                for (int j = 0; j < 4; j++)
                    acc[i][j] += a[i] * b[j];
        }
        __syncthreads();
    }
#pragma unroll
    for (int i = 0; i < 8; i++) {
        int row = bBase + ty * 8 + i;
        float4 v = make_float4(acc[i][0], acc[i][1], acc[i][2], acc[i][3]);
        *reinterpret_cast<float4*>(&dst[(size_t)row * 64 + tx * 4]) = v;
    }
}

// ---------------------------------------------------------------------------
// Kernel 2a: build augmented A operand (bf16 hi/lo).
// Row b: [x(1024) | h0(1024) | xA(64) | hA(64)]
// ---------------------------------------------------------------------------
__global__ __launch_bounds__(256) void convert_A_kernel(
    const float* __restrict__ x, const float* __restrict__ h0, int B)
{
    size_t e = (size_t)blockIdx.x * 256 + threadIdx.x;
    size_t total = (size_t)B * KAUG;
    if (e >= total) return;
    int b = (int)(e / KAUG);
    int k = (int)(e % KAUG);
    float v;
    if (k < 1024)      v = x[(size_t)b * 1024 + k];
    else if (k < 2048) v = h0[(size_t)b * 1024 + (k - 1024)];
    else if (k < 2112) v = g_xA[(size_t)b * 64 + (k - 2048)];
    else               v = g_hA[(size_t)b * 64 + (k - 2112)];
    __nv_bfloat16 hi = __float2bfloat16(v);
    float rem = v - __bfloat162float(hi);
    gA_hi[e] = hi;
    gA_lo[e] = __float2bfloat16(rem);
}

// ---------------------------------------------------------------------------
// Kernel 2b: build augmented W operand (bf16 hi/lo), N reordered n' = h*4 + g.
// ---------------------------------------------------------------------------
__global__ __launch_bounds__(256) void convert_W_kernel(
    const float* __restrict__ W_i, const float* __restrict__ W_h,
    const float* __restrict__ Bi,  const float* __restrict__ Bh)
{
    size_t e = (size_t)blockIdx.x * 256 + threadIdx.x;
    if (e >= (size_t)NAUG * KAUG) return;
    int n = (int)(e / KAUG);
    int k = (int)(e % KAUG);
    int g = n & 3;
    int h = n >> 2;
    float v;
    if (k < 1024) {
        v = W_i[((size_t)g * 1024 + h) * 1024 + k];
    } else if (k < 2048) {
        v = W_h[((size_t)g * 1024 + h) * 1024 + (k - 1024)];
    } else if (k < 2112) {
        int kk = k - 2048;
        v = ((kk >> 4) == g) ? Bi[((size_t)g * 1024 + h) * 16 + (kk & 15)] : 0.f;
    } else {
        int kk = k - 2112;
        v = ((kk >> 4) == g) ? Bh[((size_t)g * 1024 + h) * 16 + (kk & 15)] : 0.f;
    }
    __nv_bfloat16 hi = __float2bfloat16(v);
    float rem = v - __bfloat162float(hi);
    gW_hi[e] = hi;
    gW_lo[e] = __float2bfloat16(rem);
}

// ---------------------------------------------------------------------------
// Main kernel: mma.sync bf16 (3-product fp32 emulation) + fused LSTM epilogue.
// CTA 128x128, K chunks of 64, 3-stage cp.async pipeline.
// Stage layout (64 KB): A_hi 16K | A_lo 16K | B_hi 16K | B_lo 16K.
// ---------------------------------------------------------------------------
static constexpr int STG = 65536;
static constexpr int OFF_A_HI = 0;
static constexpr int OFF_A_LO = 16384;
static constexpr int OFF_B_HI = 32768;
static constexpr int OFF_B_LO = 49152;
static constexpr int OFF_BIAS = 3 * STG;               // 196608
static constexpr int SMEM_DYN = OFF_BIAS + 512 + 256;  // + align slack

__device__ __forceinline__ void load_chunk(uint32_t sb, int stage, int chunk,
                                           int bBase, int nBase, int t)
{
    const uint32_t stg = sb + stage * STG;
    const int kbase = chunk * KC;
#pragma unroll
    for (int it = 0; it < 4; it++) {
        int f = t + 256 * it;              // 0..1023
        int row = f >> 3, c16 = f & 7;
        uint32_t sw = swz((uint32_t)(row * 128 + c16 * 16));
        size_t giA = (size_t)(bBase + row) * KAUG + kbase + c16 * 8;
        size_t giB = (size_t)(nBase + row) * KAUG + kbase + c16 * 8;
        cp16(stg + OFF_A_HI + sw, &gA_hi[giA]);
        cp16(stg + OFF_A_LO + sw, &gA_lo[giA]);
        cp16(stg + OFF_B_HI + sw, &gW_hi[giB]);
        cp16(stg + OFF_B_LO + sw, &gW_lo[giB]);
    }
    CP_COMMIT();
}

__global__ __launch_bounds__(256, 1) void lstm_mma_kernel(
    const float* __restrict__ c0,
    const float* __restrict__ b_i, const float* __restrict__ b_h,
    float* __restrict__ out, int B)
{
    extern __shared__ char smem_raw[];
    uint32_t sb_raw = smem_u32(smem_raw);
    uint32_t sb = (sb_raw + 127) & ~127u;
    char* smem = smem_raw + (sb - sb_raw);

    const int t = threadIdx.x;
    const int l = t & 31;
    const int wid = t >> 5;
    const int wm = wid >> 2;        // 0..1  (M: 64 rows each)
    const int wn = wid & 3;         // 0..3  (N: 32 cols each)
    const int bBase = blockIdx.x * BM;
    const int nBase = blockIdx.y * BN;

    // bias for this N tile
    float* biasp = reinterpret_cast<float*>(smem + OFF_BIAS);
    if (t < 128) {
        int n = nBase + t;
        int g = n & 3, h = n >> 2;
        biasp[t] = b_i[g * 1024 + h] + b_h[g * 1024 + h];
    }

    float acc[4][4][4];
#pragma unroll
    for (int mi = 0; mi < 4; mi++)
#pragma unroll
        for (int ni = 0; ni < 4; ni++)
#pragma unroll
            for (int e = 0; e < 4; e++) acc[mi][ni][e] = 0.f;

    // prologue: stages 0,1
    load_chunk(sb, 0, 0, bBase, nBase, t);
    load_chunk(sb, 1, 1, bBase, nBase, t);

    // Precompute per-thread ldmatrix base offsets (row component).
    const int aRow = wm * 64 + (l & 15);                       // + mi*16
    const int aC16 = (l >> 4);                                 // + s*2
    const int bRow = wn * 32 + ((l >> 4) & 1) * 8 + (l & 7);   // + p*16
    const int bC16 = ((l >> 3) & 1);                           // + s*2

    for (int i = 0; i < NCHUNK; i++) {
        if (i < NCHUNK - 1) {
            asm volatile("cp.async.wait_group 1;" ::: "memory");
        } else {
            asm volatile("cp.async.wait_group 0;" ::: "memory");
        }
        __syncthreads();
        if (i + 2 < NCHUNK) load_chunk(sb, (i + 2) % 3, i + 2, bBase, nBase, t);

        const uint32_t stg = sb + (i % 3) * STG;

#pragma unroll
        for (int s = 0; s < 4; s++) {
            uint32_t a_hi[4][4], a_lo[4][4];
#pragma unroll
            for (int mi = 0; mi < 4; mi++) {
                uint32_t o = swz((uint32_t)((aRow + mi * 16) * 128 +
                                            (aC16 + s * 2) * 16));
                LDSM_X4(a_hi[mi][0], a_hi[mi][1], a_hi[mi][2], a_hi[mi][3],
                        stg + OFF_A_HI + o);
                LDSM_X4(a_lo[mi][0], a_lo[mi][1], a_lo[mi][2], a_lo[mi][3],
                        stg + OFF_A_LO + o);
            }
            uint32_t b_hi[4][2], b_lo[4][2];
#pragma unroll
            for (int p = 0; p < 2; p++) {
                uint32_t o = swz((uint32_t)((bRow + p * 16) * 128 +
                                            (bC16 + s * 2) * 16));
                uint32_t r0, r1, r2, r3;
                LDSM_X4(r0, r1, r2, r3, stg + OFF_B_HI + o);
                b_hi[p * 2][0] = r0;     b_hi[p * 2][1] = r1;
                b_hi[p * 2 + 1][0] = r2; b_hi[p * 2 + 1][1] = r3;
                LDSM_X4(r0, r1, r2, r3, stg + OFF_B_LO + o);
                b_lo[p * 2][0] = r0;     b_lo[p * 2][1] = r1;
                b_lo[p * 2 + 1][0] = r2; b_lo[p * 2 + 1][1] = r3;
            }
            // Product-major ordering: 16 independent MMAs between reuses of
            // any accumulator -> no RAW stall chains.
#pragma unroll
            for (int mi = 0; mi < 4; mi++)
#pragma unroll
                for (int ni = 0; ni < 4; ni++)
                    MMA_BF16(acc[mi][ni], a_hi[mi], b_hi[ni]);
#pragma unroll
            for (int mi = 0; mi < 4; mi++)
#pragma unroll
                for (int ni = 0; ni < 4; ni++)
                    MMA_BF16(acc[mi][ni], a_hi[mi], b_lo[ni]);
#pragma unroll
            for (int mi = 0; mi < 4; mi++)
#pragma unroll
                for (int ni = 0; ni < 4; ni++)
                    MMA_BF16(acc[mi][ni], a_lo[mi], b_hi[ni]);
        }
    }

    // ------------------- epilogue: stage accs through SMEM -----------------
    __syncthreads();
    float* ebuf = reinterpret_cast<float*>(smem);   // [128][132] fp32
#pragma unroll
    for (int mi = 0; mi < 4; mi++) {
#pragma unroll
        for (int ni = 0; ni < 4; ni++) {
            int r0 = wm * 64 + mi * 16 + (l >> 2);
            int c  = wn * 32 + ni * 8 + (l & 3) * 2;
            ebuf[r0 * 132 + c]           = acc[mi][ni][0];
            ebuf[r0 * 132 + c + 1]       = acc[mi][ni][1];
            ebuf[(r0 + 8) * 132 + c]     = acc[mi][ni][2];
            ebuf[(r0 + 8) * 132 + c + 1] = acc[mi][ni][3];
        }
    }
    __syncthreads();

    const int rb = t >> 1;
    const int hoff = (t & 1) * 16;
    const size_t b = (size_t)(bBase + rb);
    const int hbase = (nBase >> 2) + hoff;
    const size_t outC = (size_t)B * 1024;

    float cin[16];
#pragma unroll
    for (int q = 0; q < 4; q++) {
        float4 v = *reinterpret_cast<const float4*>(&c0[b * 1024 + hbase + q * 4]);
        cin[q * 4 + 0] = v.x; cin[q * 4 + 1] = v.y;
        cin[q * 4 + 2] = v.z; cin[q * 4 + 3] = v.w;
    }

    float hv[16], cv[16];
#pragma unroll
    for (int j = 0; j < 16; j++) {
        int nl = (hoff + j) * 4;
        const float* p = &ebuf[rb * 132 + nl];
        float pi = p[0] + biasp[nl + 0];
        float pf = p[1] + biasp[nl + 1];
        float pg = p[2] + biasp[nl + 2];
        float po = p[3] + biasp[nl + 3];

        float it = 1.f / (1.f + __expf(-pi));
        float ft = 1.f / (1.f + __expf(-pf));
        float gt = 1.f - 2.f / (__expf(2.f * pg) + 1.f);
        float ot = 1.f / (1.f + __expf(-po));

        float c = ft * cin[j] + it * gt;
        cv[j] = c;
        hv[j] = ot * (1.f - 2.f / (__expf(2.f * c) + 1.f));
    }
#pragma unroll
    for (int q = 0; q < 4; q++) {
        *reinterpret_cast<float4*>(&out[b * 1024 + hbase + q * 4]) =
            make_float4(hv[q * 4], hv[q * 4 + 1], hv[q * 4 + 2], hv[q * 4 + 3]);
        *reinterpret_cast<float4*>(&out[outC + b * 1024 + hbase + q * 4]) =
            make_float4(cv[q * 4], cv[q * 4 + 1], cv[q * 4 + 2], cv[q * 4 + 3]);
    }
}

// ---------------------------------------------------------------------------
extern "C" void kernel_launch(void* const* d_in, const int* in_sizes, int n_in,
                              void* d_out, int out_size)
{
    const float* x   = (const float*)d_in[0];
    const float* h0  = (const float*)d_in[1];
    const float* c0  = (const float*)d_in[2];
    const float* W_i = (const float*)d_in[3];
    const float* W_h = (const float*)d_in[4];
    const float* b_i = (const float*)d_in[5];
    const float* b_h = (const float*)d_in[6];
    const float* A_i = (const float*)d_in[7];
    const float* B_i = (const float*)d_in[8];
    const float* A_h = (const float*)d_in[9];
    const float* B_h = (const float*)d_in[10];

    const int B = in_sizes[0] / I_DIM;   // 8192

    // 1) LoRA rank-16 projections
    dim3 g1(B / 128, 2);
    lora_proj_kernel<<<g1, 256>>>(x, h0, A_i, A_h);

    // 2) Build bf16 hi/lo augmented operands
    {
        size_t elemsA = (size_t)B * KAUG;
        convert_A_kernel<<<(unsigned)((elemsA + 255) / 256), 256>>>(x, h0, B);
        size_t elemsW = (size_t)NAUG * KAUG;
        convert_W_kernel<<<(unsigned)((elemsW + 255) / 256), 256>>>(W_i, W_h, B_i, B_h);
    }

    // 3) Main tensor-core GEMM + fused LSTM epilogue
    cudaFuncSetAttribute(lstm_mma_kernel,
                         cudaFuncAttributeMaxDynamicSharedMemorySize, SMEM_DYN);
    dim3 g3(B / BM, NAUG / BN);
    lstm_mma_kernel<<<g3, 256, SMEM_DYN>>>(c0, b_i, b_h, (float*)d_out, B);
}

// round 5
// speedup vs baseline: 4.0934x; 1.2830x over previous
#include <cuda_runtime.h>
#include <cuda_fp16.h>
#include <cstdint>
#include <math.h>

// ---------------------------------------------------------------------------
// Problem constants
// ---------------------------------------------------------------------------
#define B_MAX 8192
#define I_DIM 1024
#define KAUG  2176          // 1024 (x) + 1024 (h0) + 64 (xA) + 64 (hA)
#define NAUG  4096          // 4 gates * 1024 h, reordered n' = h*4 + g
#define KC    64
#define NCHUNK 34           // KAUG / KC
#define BM 128
#define BN 128

// ---------------------------------------------------------------------------
// Device scratch (no allocations allowed)
// ---------------------------------------------------------------------------
__device__ float g_xA[B_MAX * 64];
__device__ float g_hA[B_MAX * 64];
__device__ __half gA[(size_t)B_MAX * KAUG];         // fp16 rounding of A
__device__ __half gW_hi[(size_t)NAUG * KAUG];       // fp16 hi of W
__device__ __half gW_lo[(size_t)NAUG * KAUG];       // fp16 residual of W

// ---------------------------------------------------------------------------
// Helpers
// ---------------------------------------------------------------------------
__device__ __forceinline__ uint32_t smem_u32(const void* p) {
    uint32_t a;
    asm("{ .reg .u64 t; cvta.to.shared.u64 t, %1; cvt.u32.u64 %0, t; }"
        : "=r"(a) : "l"(p));
    return a;
}

// Tiles are 128B-wide rows. Standard SW128: XOR 16B-chunk index with row&7.
__device__ __forceinline__ uint32_t swz(uint32_t o) {
    return o ^ (((o >> 7) & 7) << 4);
}

__device__ __forceinline__ void cp16(uint32_t dst, const void* src) {
    asm volatile("cp.async.cg.shared.global [%0], [%1], 16;"
                 :: "r"(dst), "l"(src));
}
#define CP_COMMIT() asm volatile("cp.async.commit_group;" ::: "memory")

#define LDSM_X4(r0, r1, r2, r3, addr)                                         \
    asm volatile("ldmatrix.sync.aligned.m8n8.x4.shared.b16 "                  \
                 "{%0,%1,%2,%3}, [%4];"                                       \
                 : "=r"(r0), "=r"(r1), "=r"(r2), "=r"(r3) : "r"(addr))

#define MMA_FP16(d, a, b)                                                     \
    asm volatile("mma.sync.aligned.m16n8k16.row.col.f32.f16.f16.f32 "         \
                 "{%0,%1,%2,%3}, {%4,%5,%6,%7}, {%8,%9}, {%0,%1,%2,%3};"      \
                 : "+f"((d)[0]), "+f"((d)[1]), "+f"((d)[2]), "+f"((d)[3])     \
                 : "r"((a)[0]), "r"((a)[1]), "r"((a)[2]), "r"((a)[3]),        \
                   "r"((b)[0]), "r"((b)[1]))

// ---------------------------------------------------------------------------
// Kernel 1: LoRA low-rank projections (fp32 SIMT; ~2 GFLOP)
// ---------------------------------------------------------------------------
__global__ __launch_bounds__(256) void lora_proj_kernel(
    const float* __restrict__ x, const float* __restrict__ h0,
    const float* __restrict__ A_i, const float* __restrict__ A_h)
{
    const int prob = blockIdx.y;
    const float* __restrict__ src = (prob == 0) ? x : h0;
    const float* __restrict__ Am  = (prob == 0) ? A_i : A_h;
    float* __restrict__ dst       = (prob == 0) ? g_xA : g_hA;

    __shared__ float As[16][128];
    __shared__ float Bs[16][64];

    const int t  = threadIdx.x;
    const int tx = t & 15;
    const int ty = t >> 4;
    const int bBase = blockIdx.x * 128;

    float acc[8][4];
#pragma unroll
    for (int i = 0; i < 8; i++)
#pragma unroll
        for (int j = 0; j < 4; j++) acc[i][j] = 0.f;

    for (int k0 = 0; k0 < 1024; k0 += 16) {
#pragma unroll
        for (int j = 0; j < 2; j++) {
            int f = t * 2 + j;
            int row = f >> 2, kq = f & 3;
            float4 v = *reinterpret_cast<const float4*>(
                &src[(size_t)(bBase + row) * 1024 + k0 + kq * 4]);
            As[kq * 4 + 0][row] = v.x; As[kq * 4 + 1][row] = v.y;
            As[kq * 4 + 2][row] = v.z; As[kq * 4 + 3][row] = v.w;
        }
        {
            int n = t >> 2, kq = t & 3;
            float4 v = *reinterpret_cast<const float4*>(
                &Am[(size_t)n * 1024 + k0 + kq * 4]);
            Bs[kq * 4 + 0][n] = v.x; Bs[kq * 4 + 1][n] = v.y;
            Bs[kq * 4 + 2][n] = v.z; Bs[kq * 4 + 3][n] = v.w;
        }
        __syncthreads();
#pragma unroll
        for (int kk = 0; kk < 16; kk++) {
            float a[8], b[4];
            *reinterpret_cast<float4*>(&a[0]) =
                *reinterpret_cast<const float4*>(&As[kk][ty * 8]);
            *reinterpret_cast<float4*>(&a[4]) =
                *reinterpret_cast<const float4*>(&As[kk][ty * 8 + 4]);
            *reinterpret_cast<float4*>(&b[0]) =
                *reinterpret_cast<const float4*>(&Bs[kk][tx * 4]);
#pragma unroll
            for (int i = 0; i < 8; i++)
#pragma unroll
                for (int j = 0; j < 4; j++)
                    acc[i][j] += a[i] * b[j];
        }
        __syncthreads();
    }
#pragma unroll
    for (int i = 0; i < 8; i++) {
        int row = bBase + ty * 8 + i;
        float4 v = make_float4(acc[i][0], acc[i][1], acc[i][2], acc[i][3]);
        *reinterpret_cast<float4*>(&dst[(size_t)row * 64 + tx * 4]) = v;
    }
}

// ---------------------------------------------------------------------------
// Kernel 2a: build augmented A operand (fp16 rounding).
// Row b: [x(1024) | h0(1024) | xA(64) | hA(64)]
// ---------------------------------------------------------------------------
__global__ __launch_bounds__(256) void convert_A_kernel(
    const float* __restrict__ x, const float* __restrict__ h0, int B)
{
    size_t e = (size_t)blockIdx.x * 256 + threadIdx.x;
    size_t total = (size_t)B * KAUG;
    if (e >= total) return;
    int b = (int)(e / KAUG);
    int k = (int)(e % KAUG);
    float v;
    if (k < 1024)      v = x[(size_t)b * 1024 + k];
    else if (k < 2048) v = h0[(size_t)b * 1024 + (k - 1024)];
    else if (k < 2112) v = g_xA[(size_t)b * 64 + (k - 2048)];
    else               v = g_hA[(size_t)b * 64 + (k - 2112)];
    gA[e] = __float2half(v);
}

// ---------------------------------------------------------------------------
// Kernel 2b: build augmented W operand (fp16 hi/lo), N reordered n' = h*4 + g.
// ---------------------------------------------------------------------------
__global__ __launch_bounds__(256) void convert_W_kernel(
    const float* __restrict__ W_i, const float* __restrict__ W_h,
    const float* __restrict__ Bi,  const float* __restrict__ Bh)
{
    size_t e = (size_t)blockIdx.x * 256 + threadIdx.x;
    if (e >= (size_t)NAUG * KAUG) return;
    int n = (int)(e / KAUG);
    int k = (int)(e % KAUG);
    int g = n & 3;
    int h = n >> 2;
    float v;
    if (k < 1024) {
        v = W_i[((size_t)g * 1024 + h) * 1024 + k];
    } else if (k < 2048) {
        v = W_h[((size_t)g * 1024 + h) * 1024 + (k - 1024)];
    } else if (k < 2112) {
        int kk = k - 2048;
        v = ((kk >> 4) == g) ? Bi[((size_t)g * 1024 + h) * 16 + (kk & 15)] : 0.f;
    } else {
        int kk = k - 2112;
        v = ((kk >> 4) == g) ? Bh[((size_t)g * 1024 + h) * 16 + (kk & 15)] : 0.f;
    }
    __half hi = __float2half(v);
    float rem = v - __half2float(hi);
    gW_hi[e] = hi;
    gW_lo[e] = __float2half(rem);
}

// ---------------------------------------------------------------------------
// Main kernel: mma.sync fp16 (2-product fp16-split emulation) + fused LSTM.
// CTA 128x128, K chunks of 64, 3-stage cp.async pipeline.
// Stage layout (48 KB): A 16K | B_hi 16K | B_lo 16K.
// ---------------------------------------------------------------------------
static constexpr int STG = 49152;
static constexpr int OFF_A    = 0;
static constexpr int OFF_B_HI = 16384;
static constexpr int OFF_B_LO = 32768;
static constexpr int OFF_BIAS = 3 * STG;               // 147456
static constexpr int SMEM_DYN = OFF_BIAS + 512 + 256;  // + align slack

__device__ __forceinline__ void load_chunk(uint32_t sb, int stage, int chunk,
                                           int bBase, int nBase, int t)
{
    const uint32_t stg = sb + stage * STG;
    const int kbase = chunk * KC;
#pragma unroll
    for (int it = 0; it < 4; it++) {
        int f = t + 256 * it;              // 0..1023
        int row = f >> 3, c16 = f & 7;
        uint32_t sw = swz((uint32_t)(row * 128 + c16 * 16));
        size_t giA = (size_t)(bBase + row) * KAUG + kbase + c16 * 8;
        size_t giB = (size_t)(nBase + row) * KAUG + kbase + c16 * 8;
        cp16(stg + OFF_A    + sw, &gA[giA]);
        cp16(stg + OFF_B_HI + sw, &gW_hi[giB]);
        cp16(stg + OFF_B_LO + sw, &gW_lo[giB]);
    }
    CP_COMMIT();
}

__global__ __launch_bounds__(256, 1) void lstm_mma_kernel(
    const float* __restrict__ c0,
    const float* __restrict__ b_i, const float* __restrict__ b_h,
    float* __restrict__ out, int B)
{
    extern __shared__ char smem_raw[];
    uint32_t sb_raw = smem_u32(smem_raw);
    uint32_t sb = (sb_raw + 127) & ~127u;
    char* smem = smem_raw + (sb - sb_raw);

    const int t = threadIdx.x;
    const int l = t & 31;
    const int wid = t >> 5;
    const int wm = wid >> 2;        // 0..1  (M: 64 rows each)
    const int wn = wid & 3;         // 0..3  (N: 32 cols each)
    const int bBase = blockIdx.x * BM;
    const int nBase = blockIdx.y * BN;

    // bias for this N tile
    float* biasp = reinterpret_cast<float*>(smem + OFF_BIAS);
    if (t < 128) {
        int n = nBase + t;
        int g = n & 3, h = n >> 2;
        biasp[t] = b_i[g * 1024 + h] + b_h[g * 1024 + h];
    }

    float acc[4][4][4];
#pragma unroll
    for (int mi = 0; mi < 4; mi++)
#pragma unroll
        for (int ni = 0; ni < 4; ni++)
#pragma unroll
            for (int e = 0; e < 4; e++) acc[mi][ni][e] = 0.f;

    // prologue: stages 0,1
    load_chunk(sb, 0, 0, bBase, nBase, t);
    load_chunk(sb, 1, 1, bBase, nBase, t);

    // Per-thread ldmatrix base offsets.
    const int aRow = wm * 64 + (l & 15);                       // + mi*16
    const int aC16 = (l >> 4);                                 // + s*2
    const int bRow = wn * 32 + ((l >> 4) & 1) * 8 + (l & 7);   // + p*16
    const int bC16 = ((l >> 3) & 1);                           // + s*2

    // Double-buffered fragments across the 4 k-steps of a chunk.
    uint32_t af[2][4][4], bh[2][4][2], bl[2][4][2];

    for (int i = 0; i < NCHUNK; i++) {
        if (i < NCHUNK - 1) {
            asm volatile("cp.async.wait_group 1;" ::: "memory");
        } else {
            asm volatile("cp.async.wait_group 0;" ::: "memory");
        }
        __syncthreads();
        if (i + 2 < NCHUNK) load_chunk(sb, (i + 2) % 3, i + 2, bBase, nBase, t);

        const uint32_t stg = sb + (i % 3) * STG;

        // load fragments for s = 0 into buffer 0
#pragma unroll
        for (int mi = 0; mi < 4; mi++) {
            uint32_t o = swz((uint32_t)((aRow + mi * 16) * 128 + aC16 * 16));
            LDSM_X4(af[0][mi][0], af[0][mi][1], af[0][mi][2], af[0][mi][3],
                    stg + OFF_A + o);
        }
#pragma unroll
        for (int p = 0; p < 2; p++) {
            uint32_t o = swz((uint32_t)((bRow + p * 16) * 128 + bC16 * 16));
            uint32_t r0, r1, r2, r3;
            LDSM_X4(r0, r1, r2, r3, stg + OFF_B_HI + o);
            bh[0][p * 2][0] = r0;     bh[0][p * 2][1] = r1;
            bh[0][p * 2 + 1][0] = r2; bh[0][p * 2 + 1][1] = r3;
            LDSM_X4(r0, r1, r2, r3, stg + OFF_B_LO + o);
            bl[0][p * 2][0] = r0;     bl[0][p * 2][1] = r1;
            bl[0][p * 2 + 1][0] = r2; bl[0][p * 2 + 1][1] = r3;
        }

#pragma unroll
        for (int s = 0; s < 4; s++) {
            const int cur = s & 1;
            if (s < 3) {
                const int nxt = cur ^ 1;
#pragma unroll
                for (int mi = 0; mi < 4; mi++) {
                    uint32_t o = swz((uint32_t)((aRow + mi * 16) * 128 +
                                                (aC16 + (s + 1) * 2) * 16));
                    LDSM_X4(af[nxt][mi][0], af[nxt][mi][1],
                            af[nxt][mi][2], af[nxt][mi][3], stg + OFF_A + o);
                }
#pragma unroll
                for (int p = 0; p < 2; p++) {
                    uint32_t o = swz((uint32_t)((bRow + p * 16) * 128 +
                                                (bC16 + (s + 1) * 2) * 16));
                    uint32_t r0, r1, r2, r3;
                    LDSM_X4(r0, r1, r2, r3, stg + OFF_B_HI + o);
                    bh[nxt][p * 2][0] = r0;     bh[nxt][p * 2][1] = r1;
                    bh[nxt][p * 2 + 1][0] = r2; bh[nxt][p * 2 + 1][1] = r3;
                    LDSM_X4(r0, r1, r2, r3, stg + OFF_B_LO + o);
                    bl[nxt][p * 2][0] = r0;     bl[nxt][p * 2][1] = r1;
                    bl[nxt][p * 2 + 1][0] = r2; bl[nxt][p * 2 + 1][1] = r3;
                }
            }
            // Product-major: 16 independent MMAs between accumulator reuses.
#pragma unroll
            for (int mi = 0; mi < 4; mi++)
#pragma unroll
                for (int ni = 0; ni < 4; ni++)
                    MMA_FP16(acc[mi][ni], af[cur][mi], bh[cur][ni]);
#pragma unroll
            for (int mi = 0; mi < 4; mi++)
#pragma unroll
                for (int ni = 0; ni < 4; ni++)
                    MMA_FP16(acc[mi][ni], af[cur][mi], bl[cur][ni]);
        }
    }

    // ------------------- epilogue: stage accs through SMEM -----------------
    __syncthreads();
    float* ebuf = reinterpret_cast<float*>(smem);   // [128][132] fp32
#pragma unroll
    for (int mi = 0; mi < 4; mi++) {
#pragma unroll
        for (int ni = 0; ni < 4; ni++) {
            int r0 = wm * 64 + mi * 16 + (l >> 2);
            int c  = wn * 32 + ni * 8 + (l & 3) * 2;
            ebuf[r0 * 132 + c]           = acc[mi][ni][0];
            ebuf[r0 * 132 + c + 1]       = acc[mi][ni][1];
            ebuf[(r0 + 8) * 132 + c]     = acc[mi][ni][2];
            ebuf[(r0 + 8) * 132 + c + 1] = acc[mi][ni][3];
        }
    }
    __syncthreads();

    const int rb = t >> 1;
    const int hoff = (t & 1) * 16;
    const size_t b = (size_t)(bBase + rb);
    const int hbase = (nBase >> 2) + hoff;
    const size_t outC = (size_t)B * 1024;

    float cin[16];
#pragma unroll
    for (int q = 0; q < 4; q++) {
        float4 v = *reinterpret_cast<const float4*>(&c0[b * 1024 + hbase + q * 4]);
        cin[q * 4 + 0] = v.x; cin[q * 4 + 1] = v.y;
        cin[q * 4 + 2] = v.z; cin[q * 4 + 3] = v.w;
    }

    float hv[16], cv[16];
#pragma unroll
    for (int j = 0; j < 16; j++) {
        int nl = (hoff + j) * 4;
        const float* p = &ebuf[rb * 132 + nl];
        float pi = p[0] + biasp[nl + 0];
        float pf = p[1] + biasp[nl + 1];
        float pg = p[2] + biasp[nl + 2];
        float po = p[3] + biasp[nl + 3];

        float it = 1.f / (1.f + __expf(-pi));
        float ft = 1.f / (1.f + __expf(-pf));
        float gt = 1.f - 2.f / (__expf(2.f * pg) + 1.f);
        float ot = 1.f / (1.f + __expf(-po));

        float c = ft * cin[j] + it * gt;
        cv[j] = c;
        hv[j] = ot * (1.f - 2.f / (__expf(2.f * c) + 1.f));
    }
#pragma unroll
    for (int q = 0; q < 4; q++) {
        *reinterpret_cast<float4*>(&out[b * 1024 + hbase + q * 4]) =
            make_float4(hv[q * 4], hv[q * 4 + 1], hv[q * 4 + 2], hv[q * 4 + 3]);
        *reinterpret_cast<float4*>(&out[outC + b * 1024 + hbase + q * 4]) =
            make_float4(cv[q * 4], cv[q * 4 + 1], cv[q * 4 + 2], cv[q * 4 + 3]);
    }
}

// ---------------------------------------------------------------------------
extern "C" void kernel_launch(void* const* d_in, const int* in_sizes, int n_in,
                              void* d_out, int out_size)
{
    const float* x   = (const float*)d_in[0];
    const float* h0  = (const float*)d_in[1];
    const float* c0  = (const float*)d_in[2];
    const float* W_i = (const float*)d_in[3];
    const float* W_h = (const float*)d_in[4];
    const float* b_i = (const float*)d_in[5];
    const float* b_h = (const float*)d_in[6];
    const float* A_i = (const float*)d_in[7];
    const float* B_i = (const float*)d_in[8];
    const float* A_h = (const float*)d_in[9];
    const float* B_h = (const float*)d_in[10];

    const int B = in_sizes[0] / I_DIM;   // 8192

    // 1) LoRA rank-16 projections
    dim3 g1(B / 128, 2);
    lora_proj_kernel<<<g1, 256>>>(x, h0, A_i, A_h);

    // 2) Build fp16 operands (A rounded; W split hi/lo)
    {
        size_t elemsA = (size_t)B * KAUG;
        convert_A_kernel<<<(unsigned)((elemsA + 255) / 256), 256>>>(x, h0, B);
        size_t elemsW = (size_t)NAUG * KAUG;
        convert_W_kernel<<<(unsigned)((elemsW + 255) / 256), 256>>>(W_i, W_h, B_i, B_h);
    }

    // 3) Main tensor-core GEMM + fused LSTM epilogue
    cudaFuncSetAttribute(lstm_mma_kernel,
                         cudaFuncAttributeMaxDynamicSharedMemorySize, SMEM_DYN);
    dim3 g3(B / BM, NAUG / BN);
    lstm_mma_kernel<<<g3, 256, SMEM_DYN>>>(c0, b_i, b_h, (float*)d_out, B);
}

// round 6
// speedup vs baseline: 5.9519x; 1.4540x over previous
#include <cuda_runtime.h>
#include <cuda_fp16.h>
#include <cstdint>
#include <math.h>

// ---------------------------------------------------------------------------
// Problem constants
// ---------------------------------------------------------------------------
#define B_MAX 8192
#define I_DIM 1024
#define KAUG  2176          // 1024 (x) + 1024 (h0) + 64 (xA) + 64 (hA)
#define NAUG  4096          // 4 gates * 1024 h, reordered n' = h*4 + g
#define KC    64
#define NCHUNK 34           // KAUG / KC
#define BM 128
#define BN 128

// ---------------------------------------------------------------------------
// Device scratch (no allocations allowed)
// ---------------------------------------------------------------------------
__device__ float g_xA[B_MAX * 64];
__device__ float g_hA[B_MAX * 64];
__device__ __half gA[(size_t)B_MAX * KAUG];         // fp16 rounding of A
__device__ __half gW[(size_t)NAUG * KAUG];          // fp16 rounding of W

// ---------------------------------------------------------------------------
// Helpers
// ---------------------------------------------------------------------------
__device__ __forceinline__ uint32_t smem_u32(const void* p) {
    uint32_t a;
    asm("{ .reg .u64 t; cvta.to.shared.u64 t, %1; cvt.u32.u64 %0, t; }"
        : "=r"(a) : "l"(p));
    return a;
}

// Tiles are 128B-wide rows. Standard SW128: XOR 16B-chunk index with row&7.
__device__ __forceinline__ uint32_t swz(uint32_t o) {
    return o ^ (((o >> 7) & 7) << 4);
}

__device__ __forceinline__ void cp16(uint32_t dst, const void* src) {
    asm volatile("cp.async.cg.shared.global [%0], [%1], 16;"
                 :: "r"(dst), "l"(src));
}
#define CP_COMMIT() asm volatile("cp.async.commit_group;" ::: "memory")

#define LDSM_X4(r0, r1, r2, r3, addr)                                         \
    asm volatile("ldmatrix.sync.aligned.m8n8.x4.shared.b16 "                  \
                 "{%0,%1,%2,%3}, [%4];"                                       \
                 : "=r"(r0), "=r"(r1), "=r"(r2), "=r"(r3) : "r"(addr))

#define MMA_FP16(d, a, b)                                                     \
    asm volatile("mma.sync.aligned.m16n8k16.row.col.f32.f16.f16.f32 "         \
                 "{%0,%1,%2,%3}, {%4,%5,%6,%7}, {%8,%9}, {%0,%1,%2,%3};"      \
                 : "+f"((d)[0]), "+f"((d)[1]), "+f"((d)[2]), "+f"((d)[3])     \
                 : "r"((a)[0]), "r"((a)[1]), "r"((a)[2]), "r"((a)[3]),        \
                   "r"((b)[0]), "r"((b)[1]))

// ---------------------------------------------------------------------------
// Kernel 1: LoRA low-rank projections (fp32 SIMT; ~2 GFLOP)
// ---------------------------------------------------------------------------
__global__ __launch_bounds__(256) void lora_proj_kernel(
    const float* __restrict__ x, const float* __restrict__ h0,
    const float* __restrict__ A_i, const float* __restrict__ A_h)
{
    const int prob = blockIdx.y;
    const float* __restrict__ src = (prob == 0) ? x : h0;
    const float* __restrict__ Am  = (prob == 0) ? A_i : A_h;
    float* __restrict__ dst       = (prob == 0) ? g_xA : g_hA;

    __shared__ float As[16][128];
    __shared__ float Bs[16][64];

    const int t  = threadIdx.x;
    const int tx = t & 15;
    const int ty = t >> 4;
    const int bBase = blockIdx.x * 128;

    float acc[8][4];
#pragma unroll
    for (int i = 0; i < 8; i++)
#pragma unroll
        for (int j = 0; j < 4; j++) acc[i][j] = 0.f;

    for (int k0 = 0; k0 < 1024; k0 += 16) {
#pragma unroll
        for (int j = 0; j < 2; j++) {
            int f = t * 2 + j;
            int row = f >> 2, kq = f & 3;
            float4 v = *reinterpret_cast<const float4*>(
                &src[(size_t)(bBase + row) * 1024 + k0 + kq * 4]);
            As[kq * 4 + 0][row] = v.x; As[kq * 4 + 1][row] = v.y;
            As[kq * 4 + 2][row] = v.z; As[kq * 4 + 3][row] = v.w;
        }
        {
            int n = t >> 2, kq = t & 3;
            float4 v = *reinterpret_cast<const float4*>(
                &Am[(size_t)n * 1024 + k0 + kq * 4]);
            Bs[kq * 4 + 0][n] = v.x; Bs[kq * 4 + 1][n] = v.y;
            Bs[kq * 4 + 2][n] = v.z; Bs[kq * 4 + 3][n] = v.w;
        }
        __syncthreads();
#pragma unroll
        for (int kk = 0; kk < 16; kk++) {
            float a[8], b[4];
            *reinterpret_cast<float4*>(&a[0]) =
                *reinterpret_cast<const float4*>(&As[kk][ty * 8]);
            *reinterpret_cast<float4*>(&a[4]) =
                *reinterpret_cast<const float4*>(&As[kk][ty * 8 + 4]);
            *reinterpret_cast<float4*>(&b[0]) =
                *reinterpret_cast<const float4*>(&Bs[kk][tx * 4]);
#pragma unroll
            for (int i = 0; i < 8; i++)
#pragma unroll
                for (int j = 0; j < 4; j++)
                    acc[i][j] += a[i] * b[j];
        }
        __syncthreads();
    }
#pragma unroll
    for (int i = 0; i < 8; i++) {
        int row = bBase + ty * 8 + i;
        float4 v = make_float4(acc[i][0], acc[i][1], acc[i][2], acc[i][3]);
        *reinterpret_cast<float4*>(&dst[(size_t)row * 64 + tx * 4]) = v;
    }
}

// ---------------------------------------------------------------------------
// Kernel 2a: build augmented A operand (fp16 rounding).
// Row b: [x(1024) | h0(1024) | xA(64) | hA(64)]
// ---------------------------------------------------------------------------
__global__ __launch_bounds__(256) void convert_A_kernel(
    const float* __restrict__ x, const float* __restrict__ h0, int B)
{
    size_t e = (size_t)blockIdx.x * 256 + threadIdx.x;
    size_t total = (size_t)B * KAUG;
    if (e >= total) return;
    int b = (int)(e / KAUG);
    int k = (int)(e % KAUG);
    float v;
    if (k < 1024)      v = x[(size_t)b * 1024 + k];
    else if (k < 2048) v = h0[(size_t)b * 1024 + (k - 1024)];
    else if (k < 2112) v = g_xA[(size_t)b * 64 + (k - 2048)];
    else               v = g_hA[(size_t)b * 64 + (k - 2112)];
    gA[e] = __float2half(v);
}

// ---------------------------------------------------------------------------
// Kernel 2b: build augmented W operand (fp16 rounding), N reordered n'=h*4+g.
// ---------------------------------------------------------------------------
__global__ __launch_bounds__(256) void convert_W_kernel(
    const float* __restrict__ W_i, const float* __restrict__ W_h,
    const float* __restrict__ Bi,  const float* __restrict__ Bh)
{
    size_t e = (size_t)blockIdx.x * 256 + threadIdx.x;
    if (e >= (size_t)NAUG * KAUG) return;
    int n = (int)(e / KAUG);
    int k = (int)(e % KAUG);
    int g = n & 3;
    int h = n >> 2;
    float v;
    if (k < 1024) {
        v = W_i[((size_t)g * 1024 + h) * 1024 + k];
    } else if (k < 2048) {
        v = W_h[((size_t)g * 1024 + h) * 1024 + (k - 1024)];
    } else if (k < 2112) {
        int kk = k - 2048;
        v = ((kk >> 4) == g) ? Bi[((size_t)g * 1024 + h) * 16 + (kk & 15)] : 0.f;
    } else {
        int kk = k - 2112;
        v = ((kk >> 4) == g) ? Bh[((size_t)g * 1024 + h) * 16 + (kk & 15)] : 0.f;
    }
    gW[e] = __float2half(v);
}

// ---------------------------------------------------------------------------
// Main kernel: single-product fp16 mma.sync + fused LSTM epilogue.
// CTA 128x128, K chunks of 64, 4-stage cp.async pipeline (prefetch dist 3).
// Stage layout (32 KB): A 16K | B 16K.
// ---------------------------------------------------------------------------
static constexpr int STG = 32768;
static constexpr int OFF_A = 0;
static constexpr int OFF_B = 16384;
static constexpr int OFF_BIAS = 4 * STG;               // 131072
static constexpr int SMEM_DYN = OFF_BIAS + 512 + 256;  // + align slack

__device__ __forceinline__ void load_chunk(uint32_t sb, int stage, int chunk,
                                           int bBase, int nBase, int t)
{
    const uint32_t stg = sb + stage * STG;
    const int kbase = chunk * KC;
#pragma unroll
    for (int it = 0; it < 4; it++) {
        int f = t + 256 * it;              // 0..1023
        int row = f >> 3, c16 = f & 7;
        uint32_t sw = swz((uint32_t)(row * 128 + c16 * 16));
        size_t giA = (size_t)(bBase + row) * KAUG + kbase + c16 * 8;
        size_t giB = (size_t)(nBase + row) * KAUG + kbase + c16 * 8;
        cp16(stg + OFF_A + sw, &gA[giA]);
        cp16(stg + OFF_B + sw, &gW[giB]);
    }
    CP_COMMIT();
}

__global__ __launch_bounds__(256, 1) void lstm_mma_kernel(
    const float* __restrict__ c0,
    const float* __restrict__ b_i, const float* __restrict__ b_h,
    float* __restrict__ out, int B)
{
    extern __shared__ char smem_raw[];
    uint32_t sb_raw = smem_u32(smem_raw);
    uint32_t sb = (sb_raw + 127) & ~127u;
    char* smem = smem_raw + (sb - sb_raw);

    const int t = threadIdx.x;
    const int l = t & 31;
    const int wid = t >> 5;
    const int wm = wid >> 2;        // 0..1  (M: 64 rows each)
    const int wn = wid & 3;         // 0..3  (N: 32 cols each)
    const int bBase = blockIdx.x * BM;
    const int nBase = blockIdx.y * BN;

    // bias for this N tile
    float* biasp = reinterpret_cast<float*>(smem + OFF_BIAS);
    if (t < 128) {
        int n = nBase + t;
        int g = n & 3, h = n >> 2;
        biasp[t] = b_i[g * 1024 + h] + b_h[g * 1024 + h];
    }

    float acc[4][4][4];
#pragma unroll
    for (int mi = 0; mi < 4; mi++)
#pragma unroll
        for (int ni = 0; ni < 4; ni++)
#pragma unroll
            for (int e = 0; e < 4; e++) acc[mi][ni][e] = 0.f;

    // prologue: stages 0,1,2
    load_chunk(sb, 0, 0, bBase, nBase, t);
    load_chunk(sb, 1, 1, bBase, nBase, t);
    load_chunk(sb, 2, 2, bBase, nBase, t);

    // Per-thread ldmatrix base offsets.
    const int aRow = wm * 64 + (l & 15);                       // + mi*16
    const int aC16 = (l >> 4);                                 // + s*2
    const int bRow = wn * 32 + ((l >> 4) & 1) * 8 + (l & 7);   // + p*16
    const int bC16 = ((l >> 3) & 1);                           // + s*2

    // Double-buffered fragments across the 4 k-steps of a chunk.
    uint32_t af[2][4][4], bf[2][4][2];

    for (int i = 0; i < NCHUNK; i++) {
        if (i < NCHUNK - 3) {
            asm volatile("cp.async.wait_group 2;" ::: "memory");
        } else if (i < NCHUNK - 1) {
            asm volatile("cp.async.wait_group 1;" ::: "memory");
        } else {
            asm volatile("cp.async.wait_group 0;" ::: "memory");
        }
        __syncthreads();
        if (i + 3 < NCHUNK) load_chunk(sb, (i + 3) & 3, i + 3, bBase, nBase, t);

        const uint32_t stg = sb + (i & 3) * STG;

        // load fragments for s = 0 into buffer 0
#pragma unroll
        for (int mi = 0; mi < 4; mi++) {
            uint32_t o = swz((uint32_t)((aRow + mi * 16) * 128 + aC16 * 16));
            LDSM_X4(af[0][mi][0], af[0][mi][1], af[0][mi][2], af[0][mi][3],
                    stg + OFF_A + o);
        }
#pragma unroll
        for (int p = 0; p < 2; p++) {
            uint32_t o = swz((uint32_t)((bRow + p * 16) * 128 + bC16 * 16));
            uint32_t r0, r1, r2, r3;
            LDSM_X4(r0, r1, r2, r3, stg + OFF_B + o);
            bf[0][p * 2][0] = r0;     bf[0][p * 2][1] = r1;
            bf[0][p * 2 + 1][0] = r2; bf[0][p * 2 + 1][1] = r3;
        }

#pragma unroll
        for (int s = 0; s < 4; s++) {
            const int cur = s & 1;
            if (s < 3) {
                const int nxt = cur ^ 1;
#pragma unroll
                for (int mi = 0; mi < 4; mi++) {
                    uint32_t o = swz((uint32_t)((aRow + mi * 16) * 128 +
                                                (aC16 + (s + 1) * 2) * 16));
                    LDSM_X4(af[nxt][mi][0], af[nxt][mi][1],
                            af[nxt][mi][2], af[nxt][mi][3], stg + OFF_A + o);
                }
#pragma unroll
                for (int p = 0; p < 2; p++) {
                    uint32_t o = swz((uint32_t)((bRow + p * 16) * 128 +
                                                (bC16 + (s + 1) * 2) * 16));
                    uint32_t r0, r1, r2, r3;
                    LDSM_X4(r0, r1, r2, r3, stg + OFF_B + o);
                    bf[nxt][p * 2][0] = r0;     bf[nxt][p * 2][1] = r1;
                    bf[nxt][p * 2 + 1][0] = r2; bf[nxt][p * 2 + 1][1] = r3;
                }
            }
            // 16 independent MMAs.
#pragma unroll
            for (int mi = 0; mi < 4; mi++)
#pragma unroll
                for (int ni = 0; ni < 4; ni++)
                    MMA_FP16(acc[mi][ni], af[cur][mi], bf[cur][ni]);
        }
    }

    // ------------------- epilogue: stage accs through SMEM -----------------
    __syncthreads();
    float* ebuf = reinterpret_cast<float*>(smem);   // [128][132] fp32
#pragma unroll
    for (int mi = 0; mi < 4; mi++) {
#pragma unroll
        for (int ni = 0; ni < 4; ni++) {
            int r0 = wm * 64 + mi * 16 + (l >> 2);
            int c  = wn * 32 + ni * 8 + (l & 3) * 2;
            ebuf[r0 * 132 + c]           = acc[mi][ni][0];
            ebuf[r0 * 132 + c + 1]       = acc[mi][ni][1];
            ebuf[(r0 + 8) * 132 + c]     = acc[mi][ni][2];
            ebuf[(r0 + 8) * 132 + c + 1] = acc[mi][ni][3];
        }
    }
    __syncthreads();

    const int rb = t >> 1;
    const int hoff = (t & 1) * 16;
    const size_t b = (size_t)(bBase + rb);
    const int hbase = (nBase >> 2) + hoff;
    const size_t outC = (size_t)B * 1024;

    float cin[16];
#pragma unroll
    for (int q = 0; q < 4; q++) {
        float4 v = *reinterpret_cast<const float4*>(&c0[b * 1024 + hbase + q * 4]);
        cin[q * 4 + 0] = v.x; cin[q * 4 + 1] = v.y;
        cin[q * 4 + 2] = v.z; cin[q * 4 + 3] = v.w;
    }

    float hv[16], cv[16];
#pragma unroll
    for (int j = 0; j < 16; j++) {
        int nl = (hoff + j) * 4;
        const float* p = &ebuf[rb * 132 + nl];
        float pi = p[0] + biasp[nl + 0];
        float pf = p[1] + biasp[nl + 1];
        float pg = p[2] + biasp[nl + 2];
        float po = p[3] + biasp[nl + 3];

        float it = 1.f / (1.f + __expf(-pi));
        float ft = 1.f / (1.f + __expf(-pf));
        float gt = 1.f - 2.f / (__expf(2.f * pg) + 1.f);
        float ot = 1.f / (1.f + __expf(-po));

        float c = ft * cin[j] + it * gt;
        cv[j] = c;
        hv[j] = ot * (1.f - 2.f / (__expf(2.f * c) + 1.f));
    }
#pragma unroll
    for (int q = 0; q < 4; q++) {
        *reinterpret_cast<float4*>(&out[b * 1024 + hbase + q * 4]) =
            make_float4(hv[q * 4], hv[q * 4 + 1], hv[q * 4 + 2], hv[q * 4 + 3]);
        *reinterpret_cast<float4*>(&out[outC + b * 1024 + hbase + q * 4]) =
            make_float4(cv[q * 4], cv[q * 4 + 1], cv[q * 4 + 2], cv[q * 4 + 3]);
    }
}

// ---------------------------------------------------------------------------
extern "C" void kernel_launch(void* const* d_in, const int* in_sizes, int n_in,
                              void* d_out, int out_size)
{
    const float* x   = (const float*)d_in[0];
    const float* h0  = (const float*)d_in[1];
    const float* c0  = (const float*)d_in[2];
    const float* W_i = (const float*)d_in[3];
    const float* W_h = (const float*)d_in[4];
    const float* b_i = (const float*)d_in[5];
    const float* b_h = (const float*)d_in[6];
    const float* A_i = (const float*)d_in[7];
    const float* B_i = (const float*)d_in[8];
    const float* A_h = (const float*)d_in[9];
    const float* B_h = (const float*)d_in[10];

    const int B = in_sizes[0] / I_DIM;   // 8192

    // 1) LoRA rank-16 projections
    dim3 g1(B / 128, 2);
    lora_proj_kernel<<<g1, 256>>>(x, h0, A_i, A_h);

    // 2) Build fp16 operands
    {
        size_t elemsA = (size_t)B * KAUG;
        convert_A_kernel<<<(unsigned)((elemsA + 255) / 256), 256>>>(x, h0, B);
        size_t elemsW = (size_t)NAUG * KAUG;
        convert_W_kernel<<<(unsigned)((elemsW + 255) / 256), 256>>>(W_i, W_h, B_i, B_h);
    }

    // 3) Main tensor-core GEMM + fused LSTM epilogue
    cudaFuncSetAttribute(lstm_mma_kernel,
                         cudaFuncAttributeMaxDynamicSharedMemorySize, SMEM_DYN);
    dim3 g3(B / BM, NAUG / BN);
    lstm_mma_kernel<<<g3, 256, SMEM_DYN>>>(c0, b_i, b_h, (float*)d_out, B);
}